// round 9
// baseline (speedup 1.0000x reference)
#include <cuda_runtime.h>
#include <cuda_fp16.h>
#include <math.h>
#include <stdint.h>

// InfoNCE loss: single-pass fp16 HMMA GEMM (f32 acc) + fused online LSE.
// Queries pre-scaled by 1/T in fp16; A double-buffered; fused final reduce.
// Inputs: out f32 [512,128], keys f32 [512,512,128], self_index i32 [512]
// Output: scalar f32 loss.

#define BQ      512
#define DD      128
#define KPB     512
#define NKEYS   (BQ * KPB)
#define TILEN   128
#define NTILES  (NKEYS / TILEN)      // 2048
#define INV_T   14.285714285714285f
#define NEG_BIG -1.0e30f

// ---------------- global scratch (allocation-free rule) ----------------
__device__ __align__(256) __half g_qh[BQ * DD];          // queries * INV_T, fp16
__device__ float g_pm[BQ * NTILES], g_ps[BQ * NTILES];
__device__ float g_posm[BQ * 4],    g_poss[BQ * 4];
__device__ float g_loss[BQ];
__device__ unsigned int g_done;                          // completion counter (self-resets)

// ---------------- PTX helpers ----------------
__device__ __forceinline__ uint32_t smem_u32(const void* p) {
    uint32_t a;
    asm("{ .reg .u64 t; cvta.to.shared.u64 t, %1; cvt.u32.u64 %0, t; }" : "=r"(a) : "l"(p));
    return a;
}
__device__ __forceinline__ void ldmx4(uint32_t* r, uint32_t addr) {
    asm volatile("ldmatrix.sync.aligned.m8n8.x4.shared.b16 {%0,%1,%2,%3}, [%4];"
                 : "=r"(r[0]), "=r"(r[1]), "=r"(r[2]), "=r"(r[3]) : "r"(addr));
}
__device__ __forceinline__ void hmma16816(float* c, const uint32_t* a, const uint32_t* b) {
    asm volatile("mma.sync.aligned.m16n8k16.row.col.f32.f16.f16.f32 "
                 "{%0,%1,%2,%3},{%4,%5,%6,%7},{%8,%9},{%0,%1,%2,%3};"
                 : "+f"(c[0]), "+f"(c[1]), "+f"(c[2]), "+f"(c[3])
                 : "r"(a[0]), "r"(a[1]), "r"(a[2]), "r"(a[3]), "r"(b[0]), "r"(b[1]));
}
#define CPASYNC16(s, g) asm volatile("cp.async.cg.shared.global [%0], [%1], 16;" :: "r"(s), "l"(g))
#define CP_COMMIT()     asm volatile("cp.async.commit_group;" ::: "memory")
#define CP_WAIT0()      asm volatile("cp.async.wait_group 0;" ::: "memory")

// ---------------------------------------------------------------------------
// Kernel 0: queries f32 -> fp16 * INV_T (folds temperature into A once).
// ---------------------------------------------------------------------------
__global__ __launch_bounds__(256)
void qconv(const float* __restrict__ Q)
{
    const int t = blockIdx.x * 256 + threadIdx.x;      // 4096 threads
    #pragma unroll
    for (int i = 0; i < 4; i++) {
        int f = t + i * 4096;                          // float4 index 0..16383
        float4 v = ((const float4*)Q)[f];
        __half2 h0 = __floats2half2_rn(v.x * INV_T, v.y * INV_T);
        __half2 h1 = __floats2half2_rn(v.z * INV_T, v.w * INV_T);
        ((uint2*)g_qh)[f] = make_uint2(*(uint32_t*)&h0, *(uint32_t*)&h1);
    }
}

// ---------------- SMEM layout ----------------
// tiles 128 rows x 128 fp16, padded stride 272 B (17 x 16B -> ldmatrix conflict-free)
#define TSTRIDE 272u
#define TBYTES  34816u
#define OFF_B   0u
#define OFF_A0  34816u
#define OFF_A1  69632u
#define OFF_EM  104448u                     // float [4][128]
#define OFF_ES  106496u
#define SMEM_SZ 108544u

// cp.async one 128x128 fp16 tile from global fp16 (2048 16B chunks, 8/thread)
__device__ __forceinline__ void load_a_tile(uint32_t s_a, const __half* g, int rowBase, int tid)
{
    #pragma unroll
    for (int i = 0; i < 8; i++) {
        int idx = tid + i * 256;            // 0..2047
        int r   = idx >> 4;
        int c   = idx & 15;
        const char* gp = (const char*)g + (size_t)(rowBase + r) * 256 + c * 16;
        CPASYNC16(s_a + r * TSTRIDE + c * 16, gp);
    }
}

// ---------------------------------------------------------------------------
// Kernel 1: one CTA per 128-key tile; B converted f32->f16 in-CTA (keys read
// once from DRAM); 4 m-blocks of 128 queries, A double-buffered with prefetch
// issued BEFORE the HMMA block so cp.async hides under tensor work.
// ---------------------------------------------------------------------------
__global__ __launch_bounds__(256, 2)
void gemm_lse_hmma(const float* __restrict__ Km, const int* __restrict__ sidx)
{
    extern __shared__ char smem[];
    const uint32_t sb = smem_u32(smem);
    const int tid  = threadIdx.x;
    const int wid  = tid >> 5;
    const int lane = tid & 31;
    const int tile = blockIdx.x;
    const int colBase = tile * TILEN;
    const int wm = (wid & 1) * 64;
    const int wn = (wid >> 1) * 32;
    const int nw = wid >> 1;

    float* smM = (float*)(smem + OFF_EM);
    float* smS = (float*)(smem + OFF_ES);

    // kick A(0) prefetch, then convert B tile f32 -> f16 smem (hides LDG latency)
    load_a_tile(sb + OFF_A0, g_qh, 0, tid);
    CP_COMMIT();
    #pragma unroll
    for (int i = 0; i < 16; i++) {
        int f  = tid + i * 256;             // float4 index 0..4095 (32 per row)
        int r  = f >> 5;
        int c4 = f & 31;
        float4 v = *(const float4*)(Km + (size_t)(colBase + r) * DD + c4 * 4);
        __half2 h0 = __floats2half2_rn(v.x, v.y);
        __half2 h1 = __floats2half2_rn(v.z, v.w);
        *(uint2*)(smem + OFF_B + r * TSTRIDE + c4 * 8)
            = make_uint2(*(uint32_t*)&h0, *(uint32_t*)&h1);
    }

    #pragma unroll 1
    for (int mb = 0; mb < 4; mb++) {
        CP_WAIT0();
        __syncthreads();                    // A(mb) ready; prev HMMA + combine done
        if (mb < 3) {                       // prefetch A(mb+1) under THIS mb's HMMA
            load_a_tile(sb + ((mb & 1) ? OFF_A0 : OFF_A1), g_qh, (mb + 1) * 128, tid);
            CP_COMMIT();
        }

        float acc[4][4][4];
        #pragma unroll
        for (int mi = 0; mi < 4; mi++)
            #pragma unroll
            for (int ni = 0; ni < 4; ni++)
                #pragma unroll
                for (int r = 0; r < 4; r++) acc[mi][ni][r] = 0.0f;

        const uint32_t abase = sb + ((mb & 1) ? OFF_A1 : OFF_A0);
        const uint32_t arow = abase + (wm + (lane & 15)) * TSTRIDE + (lane >> 4) * 16;
        const uint32_t brow = sb + OFF_B + (wn + (lane & 15)) * TSTRIDE + (lane >> 4) * 16;
        #pragma unroll
        for (int kk = 0; kk < 8; kk++) {                // 8 k-steps of 16 halves
            uint32_t a[4][4], bq[8];
            #pragma unroll
            for (int mi = 0; mi < 4; mi++)
                ldmx4(a[mi], arow + kk * 32 + mi * 16 * TSTRIDE);
            ldmx4(bq,     brow + kk * 32);
            ldmx4(bq + 4, brow + kk * 32 + 16 * TSTRIDE);
            uint32_t bb[4][2] = {{bq[0], bq[2]}, {bq[1], bq[3]},
                                 {bq[4], bq[6]}, {bq[5], bq[7]}};
            #pragma unroll
            for (int mi = 0; mi < 4; mi++)
                #pragma unroll
                for (int ni = 0; ni < 4; ni++)
                    hmma16816(acc[mi][ni], a[mi], bb[ni]);
        }

        // ---- epilogue: max-first per-row (max, sumexp), quad-shuffle reduce ----
        // (acc already includes 1/T via pre-scaled queries)
        #pragma unroll
        for (int mi = 0; mi < 4; mi++) {
            const int r0l = wm + mi * 16 + (lane >> 2);
            const int r1l = r0l + 8;
            const int q0 = mb * 128 + r0l, q1 = mb * 128 + r1l;
            const int msk0 = q0 * KPB + __ldg(&sidx[q0]) - colBase;
            const int msk1 = q1 * KPB + __ldg(&sidx[q1]) - colBase;
            float v0[8], v1[8];
            #pragma unroll
            for (int ni = 0; ni < 4; ni++) {
                const int c = wn + ni * 8 + 2 * (lane & 3);
                float x0 = acc[mi][ni][0]; if (c     == msk0) x0 = NEG_BIG;
                float x1 = acc[mi][ni][1]; if (c + 1 == msk0) x1 = NEG_BIG;
                float y0 = acc[mi][ni][2]; if (c     == msk1) y0 = NEG_BIG;
                float y1 = acc[mi][ni][3]; if (c + 1 == msk1) y1 = NEG_BIG;
                v0[2 * ni] = x0; v0[2 * ni + 1] = x1;
                v1[2 * ni] = y0; v1[2 * ni + 1] = y1;
            }
            float m0 = -3.0e38f, m1 = -3.0e38f;
            #pragma unroll
            for (int j = 0; j < 8; j++) { m0 = fmaxf(m0, v0[j]); m1 = fmaxf(m1, v1[j]); }
            #pragma unroll
            for (int o = 1; o < 4; o <<= 1) {           // row max over the quad
                m0 = fmaxf(m0, __shfl_xor_sync(0xFFFFFFFFu, m0, o));
                m1 = fmaxf(m1, __shfl_xor_sync(0xFFFFFFFFu, m1, o));
            }
            float s0 = 0.0f, s1 = 0.0f;
            #pragma unroll
            for (int j = 0; j < 8; j++) {
                s0 += __expf(v0[j] - m0);
                s1 += __expf(v1[j] - m1);
            }
            #pragma unroll
            for (int o = 1; o < 4; o <<= 1) {           // row sum over the quad
                s0 += __shfl_xor_sync(0xFFFFFFFFu, s0, o);
                s1 += __shfl_xor_sync(0xFFFFFFFFu, s1, o);
            }
            if ((lane & 3) == 0) {
                smM[nw * 128 + r0l] = m0; smS[nw * 128 + r0l] = s0;
                smM[nw * 128 + r1l] = m1; smS[nw * 128 + r1l] = s1;
            }
        }
        __syncthreads();
        if (tid < 128) {                    // combine 4 n-warp partials per row
            float m = -3.0e38f, s = 0.0f;
            #pragma unroll
            for (int w = 0; w < 4; w++) {
                float mo = smM[w * 128 + tid], so = smS[w * 128 + tid];
                float M = fmaxf(m, mo);
                s = s * __expf(m - M) + so * __expf(mo - M);
                m = M;
            }
            const int q = mb * 128 + tid;
            g_pm[q * NTILES + tile] = m;
            g_ps[q * NTILES + tile] = s;
            if (q == (tile >> 2)) {         // positive (own-bag) tile
                g_posm[q * 4 + (tile & 3)] = m;
                g_poss[q * 4 + (tile & 3)] = s;
            }
        }
    }
}

// ---------------------------------------------------------------------------
// Kernel 2 (fused): per query, reduce 2048 (m,s) partials -> total LSE;
// own-bag partials + 261632 exp(0) -> positive LSE; per-query loss. The last
// block to finish sums g_loss in fixed order -> mean (deterministic) and
// resets the counter for graph replay.
// ---------------------------------------------------------------------------
__global__ void reduce_all(float* __restrict__ out)
{
    __shared__ float sm[256], ss[256];
    __shared__ unsigned int is_last;
    const int b = blockIdx.x, tid = threadIdx.x;

    float m = -3.0e38f, s = 0.0f;
    for (int t = tid; t < NTILES; t += 256) {
        float mo = g_pm[b * NTILES + t], so = g_ps[b * NTILES + t];
        float M = fmaxf(m, mo);
        s = s * __expf(m - M) + so * __expf(mo - M);
        m = M;
    }
    sm[tid] = m; ss[tid] = s;
    __syncthreads();
    for (int st = 128; st > 0; st >>= 1) {
        if (tid < st) {
            float m1 = sm[tid], m2 = sm[tid + st];
            float s1 = ss[tid], s2 = ss[tid + st];
            float M = fmaxf(m1, m2);
            sm[tid] = M;
            ss[tid] = s1 * __expf(m1 - M) + s2 * __expf(m2 - M);
        }
        __syncthreads();
    }
    if (tid == 0) {
        float lse_tot = sm[0] + logf(ss[0]);

        float mp = -3.0e38f, sp = 0.0f;
        #pragma unroll
        for (int p = 0; p < 4; p++) {
            float mo = g_posm[b * 4 + p], so = g_poss[b * 4 + p];
            float M = fmaxf(mp, mo);
            sp = sp * __expf(mp - M) + so * __expf(mo - M);
            mp = M;
        }
        // s_*labels keeps negatives as exp(0)=1: B*K - K = 261632 of them
        float Mp = fmaxf(mp, 0.0f);
        float Sp = sp * __expf(mp - Mp) + 261632.0f * __expf(-Mp);
        float lse_p = Mp + logf(Sp);

        g_loss[b] = -lse_p + logf(511.0f) + lse_tot;      // num_p = 512 -> 511

        __threadfence();
        is_last = (atomicAdd(&g_done, 1u) == BQ - 1) ? 1u : 0u;
    }
    __syncthreads();
    if (is_last) {                           // final mean, fixed order (deterministic)
        __threadfence();
        sm[tid] = g_loss[tid] + g_loss[tid + 256];
        __syncthreads();
        for (int st = 128; st > 0; st >>= 1) {
            if (tid < st) sm[tid] += sm[tid + st];
            __syncthreads();
        }
        if (tid == 0) {
            out[0] = sm[0] * (1.0f / 512.0f);
            g_done = 0;                      // reset for next graph replay
        }
    }
}

// ---------------------------------------------------------------------------
extern "C" void kernel_launch(void* const* d_in, const int* in_sizes, int n_in,
                              void* d_out, int out_size)
{
    const float* Q    = (const float*)d_in[0];   // [512,128]
    const float* Km   = (const float*)d_in[1];   // [512,512,128]
    const int*   sidx = (const int*)  d_in[2];   // [512]

    cudaFuncSetAttribute(gemm_lse_hmma, cudaFuncAttributeMaxDynamicSharedMemorySize, SMEM_SZ);

    qconv<<<16, 256>>>(Q);
    gemm_lse_hmma<<<NTILES, 256, SMEM_SZ>>>(Km, sidx);
    reduce_all<<<BQ, 256>>>((float*)d_out);
}

// round 10
// speedup vs baseline: 1.0458x; 1.0458x over previous
#include <cuda_runtime.h>
#include <cuda_fp16.h>
#include <math.h>
#include <stdint.h>

// InfoNCE loss: single-pass fp16 HMMA GEMM (f32 acc) + fused online LSE.
// R6 overlap structure (A prefetch under epilogue), INV_T folded into fp16
// queries, fused single-launch final reduce.
// Inputs: out f32 [512,128], keys f32 [512,512,128], self_index i32 [512]
// Output: scalar f32 loss.

#define BQ      512
#define DD      128
#define KPB     512
#define NKEYS   (BQ * KPB)
#define TILEN   128
#define NTILES  (NKEYS / TILEN)      // 2048
#define INV_T   14.285714285714285f
#define NEG_BIG -1.0e30f

// ---------------- global scratch (allocation-free rule) ----------------
__device__ __align__(256) __half g_qh[BQ * DD];          // queries * INV_T, fp16
__device__ float g_pm[BQ * NTILES], g_ps[BQ * NTILES];
__device__ float g_posm[BQ * 4],    g_poss[BQ * 4];
__device__ float g_loss[BQ];
__device__ unsigned int g_done;                          // completion counter (self-resets)

// ---------------- PTX helpers ----------------
__device__ __forceinline__ uint32_t smem_u32(const void* p) {
    uint32_t a;
    asm("{ .reg .u64 t; cvta.to.shared.u64 t, %1; cvt.u32.u64 %0, t; }" : "=r"(a) : "l"(p));
    return a;
}
__device__ __forceinline__ void ldmx4(uint32_t* r, uint32_t addr) {
    asm volatile("ldmatrix.sync.aligned.m8n8.x4.shared.b16 {%0,%1,%2,%3}, [%4];"
                 : "=r"(r[0]), "=r"(r[1]), "=r"(r[2]), "=r"(r[3]) : "r"(addr));
}
__device__ __forceinline__ void hmma16816(float* c, const uint32_t* a, const uint32_t* b) {
    asm volatile("mma.sync.aligned.m16n8k16.row.col.f32.f16.f16.f32 "
                 "{%0,%1,%2,%3},{%4,%5,%6,%7},{%8,%9},{%0,%1,%2,%3};"
                 : "+f"(c[0]), "+f"(c[1]), "+f"(c[2]), "+f"(c[3])
                 : "r"(a[0]), "r"(a[1]), "r"(a[2]), "r"(a[3]), "r"(b[0]), "r"(b[1]));
}
#define CPASYNC16(s, g) asm volatile("cp.async.cg.shared.global [%0], [%1], 16;" :: "r"(s), "l"(g))
#define CP_COMMIT()     asm volatile("cp.async.commit_group;" ::: "memory")
#define CP_WAIT0()      asm volatile("cp.async.wait_group 0;" ::: "memory")

// ---------------------------------------------------------------------------
// Kernel 0: queries f32 -> fp16 * INV_T (folds temperature into A once).
// ---------------------------------------------------------------------------
__global__ __launch_bounds__(256)
void qconv(const float* __restrict__ Q)
{
    const int t = blockIdx.x * 256 + threadIdx.x;      // 4096 threads
    #pragma unroll
    for (int i = 0; i < 4; i++) {
        int f = t + i * 4096;                          // float4 index 0..16383
        float4 v = ((const float4*)Q)[f];
        __half2 h0 = __floats2half2_rn(v.x * INV_T, v.y * INV_T);
        __half2 h1 = __floats2half2_rn(v.z * INV_T, v.w * INV_T);
        ((uint2*)g_qh)[f] = make_uint2(*(uint32_t*)&h0, *(uint32_t*)&h1);
    }
}

// ---------------- SMEM layout ----------------
// tiles 128 rows x 128 fp16, padded stride 272 B (17 x 16B -> ldmatrix conflict-free)
#define TSTRIDE 272u
#define TBYTES  34816u
#define OFF_B   0u
#define OFF_A   34816u
#define OFF_EM  69632u                      // float [4][128]
#define OFF_ES  71680u
#define SMEM_SZ 73728u

// cp.async one 128x128 fp16 tile from global fp16 (2048 16B chunks, 8/thread)
__device__ __forceinline__ void load_a_tile(uint32_t s_a, const __half* g, int rowBase, int tid)
{
    #pragma unroll
    for (int i = 0; i < 8; i++) {
        int idx = tid + i * 256;            // 0..2047
        int r   = idx >> 4;
        int c   = idx & 15;
        const char* gp = (const char*)g + (size_t)(rowBase + r) * 256 + c * 16;
        CPASYNC16(s_a + r * TSTRIDE + c * 16, gp);
    }
}

// ---------------------------------------------------------------------------
// Kernel 1: one CTA per 128-key tile; B converted f32->f16 in-CTA (keys read
// once from DRAM); loop 4 m-blocks of 128 queries, A prefetched into the same
// buffer DURING the epilogue (LSU idle there). 8 warps, warp tile 64m x 32n.
// ---------------------------------------------------------------------------
__global__ __launch_bounds__(256, 2)
void gemm_lse_hmma(const float* __restrict__ Km, const int* __restrict__ sidx)
{
    extern __shared__ char smem[];
    const uint32_t sb = smem_u32(smem);
    const int tid  = threadIdx.x;
    const int wid  = tid >> 5;
    const int lane = tid & 31;
    const int tile = blockIdx.x;
    const int colBase = tile * TILEN;
    const int wm = (wid & 1) * 64;
    const int wn = (wid >> 1) * 32;
    const int nw = wid >> 1;

    float* smM = (float*)(smem + OFF_EM);
    float* smS = (float*)(smem + OFF_ES);

    // kick A(0) prefetch, then convert B tile f32 -> f16 smem (hides LDG latency)
    load_a_tile(sb + OFF_A, g_qh, 0, tid);
    CP_COMMIT();
    #pragma unroll
    for (int i = 0; i < 16; i++) {
        int f  = tid + i * 256;             // float4 index 0..4095 (32 per row)
        int r  = f >> 5;
        int c4 = f & 31;
        float4 v = *(const float4*)(Km + (size_t)(colBase + r) * DD + c4 * 4);
        __half2 h0 = __floats2half2_rn(v.x, v.y);
        __half2 h1 = __floats2half2_rn(v.z, v.w);
        *(uint2*)(smem + OFF_B + r * TSTRIDE + c4 * 8)
            = make_uint2(*(uint32_t*)&h0, *(uint32_t*)&h1);
    }
    CP_WAIT0();
    __syncthreads();

    #pragma unroll 1
    for (int mb = 0; mb < 4; mb++) {
        float acc[4][4][4];
        #pragma unroll
        for (int mi = 0; mi < 4; mi++)
            #pragma unroll
            for (int ni = 0; ni < 4; ni++)
                #pragma unroll
                for (int r = 0; r < 4; r++) acc[mi][ni][r] = 0.0f;

        const uint32_t arow = sb + OFF_A + (wm + (lane & 15)) * TSTRIDE + (lane >> 4) * 16;
        const uint32_t brow = sb + OFF_B + (wn + (lane & 15)) * TSTRIDE + (lane >> 4) * 16;
        #pragma unroll
        for (int kk = 0; kk < 8; kk++) {                // 8 k-steps of 16 halves
            uint32_t a[4][4], bq[8];
            #pragma unroll
            for (int mi = 0; mi < 4; mi++)
                ldmx4(a[mi], arow + kk * 32 + mi * 16 * TSTRIDE);
            ldmx4(bq,     brow + kk * 32);
            ldmx4(bq + 4, brow + kk * 32 + 16 * TSTRIDE);
            uint32_t bb[4][2] = {{bq[0], bq[2]}, {bq[1], bq[3]},
                                 {bq[4], bq[6]}, {bq[5], bq[7]}};
            #pragma unroll
            for (int mi = 0; mi < 4; mi++)
                #pragma unroll
                for (int ni = 0; ni < 4; ni++)
                    hmma16816(acc[mi][ni], a[mi], bb[ni]);
        }

        __syncthreads();                    // all warps done reading A smem
        if (mb < 3) {                       // prefetch next A under the epilogue
            load_a_tile(sb + OFF_A, g_qh, (mb + 1) * 128, tid);
            CP_COMMIT();
        }

        // ---- epilogue: max-first per-row (max, sumexp), quad-shuffle reduce ----
        // (acc already includes 1/T via pre-scaled queries)
        #pragma unroll
        for (int mi = 0; mi < 4; mi++) {
            const int r0l = wm + mi * 16 + (lane >> 2);
            const int r1l = r0l + 8;
            const int q0 = mb * 128 + r0l, q1 = mb * 128 + r1l;
            const int msk0 = q0 * KPB + __ldg(&sidx[q0]) - colBase;
            const int msk1 = q1 * KPB + __ldg(&sidx[q1]) - colBase;
            float v0[8], v1[8];
            #pragma unroll
            for (int ni = 0; ni < 4; ni++) {
                const int c = wn + ni * 8 + 2 * (lane & 3);
                float x0 = acc[mi][ni][0]; if (c     == msk0) x0 = NEG_BIG;
                float x1 = acc[mi][ni][1]; if (c + 1 == msk0) x1 = NEG_BIG;
                float y0 = acc[mi][ni][2]; if (c     == msk1) y0 = NEG_BIG;
                float y1 = acc[mi][ni][3]; if (c + 1 == msk1) y1 = NEG_BIG;
                v0[2 * ni] = x0; v0[2 * ni + 1] = x1;
                v1[2 * ni] = y0; v1[2 * ni + 1] = y1;
            }
            float m0 = -3.0e38f, m1 = -3.0e38f;
            #pragma unroll
            for (int j = 0; j < 8; j++) { m0 = fmaxf(m0, v0[j]); m1 = fmaxf(m1, v1[j]); }
            #pragma unroll
            for (int o = 1; o < 4; o <<= 1) {           // row max over the quad
                m0 = fmaxf(m0, __shfl_xor_sync(0xFFFFFFFFu, m0, o));
                m1 = fmaxf(m1, __shfl_xor_sync(0xFFFFFFFFu, m1, o));
            }
            float s0 = 0.0f, s1 = 0.0f;
            #pragma unroll
            for (int j = 0; j < 8; j++) {
                s0 += __expf(v0[j] - m0);
                s1 += __expf(v1[j] - m1);
            }
            #pragma unroll
            for (int o = 1; o < 4; o <<= 1) {           // row sum over the quad
                s0 += __shfl_xor_sync(0xFFFFFFFFu, s0, o);
                s1 += __shfl_xor_sync(0xFFFFFFFFu, s1, o);
            }
            if ((lane & 3) == 0) {
                smM[nw * 128 + r0l] = m0; smS[nw * 128 + r0l] = s0;
                smM[nw * 128 + r1l] = m1; smS[nw * 128 + r1l] = s1;
            }
        }
        __syncthreads();
        if (tid < 128) {                    // combine 4 n-warp partials per row
            float m = -3.0e38f, s = 0.0f;
            #pragma unroll
            for (int w = 0; w < 4; w++) {
                float mo = smM[w * 128 + tid], so = smS[w * 128 + tid];
                float M = fmaxf(m, mo);
                s = s * __expf(m - M) + so * __expf(mo - M);
                m = M;
            }
            const int q = mb * 128 + tid;
            g_pm[q * NTILES + tile] = m;
            g_ps[q * NTILES + tile] = s;
            if (q == (tile >> 2)) {         // positive (own-bag) tile
                g_posm[q * 4 + (tile & 3)] = m;
                g_poss[q * 4 + (tile & 3)] = s;
            }
        }
        CP_WAIT0();
        __syncthreads();                    // next A tile resident
    }
}

// ---------------------------------------------------------------------------
// Kernel 2 (fused): per query, reduce 2048 (m,s) partials -> total LSE;
// own-bag partials + 261632 exp(0) -> positive LSE; per-query loss. The last
// block to finish sums g_loss in fixed order -> mean (deterministic) and
// resets the counter for graph replay.
// ---------------------------------------------------------------------------
__global__ void reduce_all(float* __restrict__ out)
{
    __shared__ float sm[256], ss[256];
    __shared__ unsigned int is_last;
    const int b = blockIdx.x, tid = threadIdx.x;

    float m = -3.0e38f, s = 0.0f;
    for (int t = tid; t < NTILES; t += 256) {
        float mo = g_pm[b * NTILES + t], so = g_ps[b * NTILES + t];
        float M = fmaxf(m, mo);
        s = s * __expf(m - M) + so * __expf(mo - M);
        m = M;
    }
    sm[tid] = m; ss[tid] = s;
    __syncthreads();
    for (int st = 128; st > 0; st >>= 1) {
        if (tid < st) {
            float m1 = sm[tid], m2 = sm[tid + st];
            float s1 = ss[tid], s2 = ss[tid + st];
            float M = fmaxf(m1, m2);
            sm[tid] = M;
            ss[tid] = s1 * __expf(m1 - M) + s2 * __expf(m2 - M);
        }
        __syncthreads();
    }
    if (tid == 0) {
        float lse_tot = sm[0] + logf(ss[0]);

        float mp = -3.0e38f, sp = 0.0f;
        #pragma unroll
        for (int p = 0; p < 4; p++) {
            float mo = g_posm[b * 4 + p], so = g_poss[b * 4 + p];
            float M = fmaxf(mp, mo);
            sp = sp * __expf(mp - M) + so * __expf(mo - M);
            mp = M;
        }
        // s_*labels keeps negatives as exp(0)=1: B*K - K = 261632 of them
        float Mp = fmaxf(mp, 0.0f);
        float Sp = sp * __expf(mp - Mp) + 261632.0f * __expf(-Mp);
        float lse_p = Mp + logf(Sp);

        g_loss[b] = -lse_p + logf(511.0f) + lse_tot;      // num_p = 512 -> 511

        __threadfence();
        is_last = (atomicAdd(&g_done, 1u) == BQ - 1) ? 1u : 0u;
    }
    __syncthreads();
    if (is_last) {                           // final mean, fixed order (deterministic)
        __threadfence();
        sm[tid] = g_loss[tid] + g_loss[tid + 256];
        __syncthreads();
        for (int st = 128; st > 0; st >>= 1) {
            if (tid < st) sm[tid] += sm[tid + st];
            __syncthreads();
        }
        if (tid == 0) {
            out[0] = sm[0] * (1.0f / 512.0f);
            g_done = 0;                      // reset for next graph replay
        }
    }
}

// ---------------------------------------------------------------------------
extern "C" void kernel_launch(void* const* d_in, const int* in_sizes, int n_in,
                              void* d_out, int out_size)
{
    const float* Q    = (const float*)d_in[0];   // [512,128]
    const float* Km   = (const float*)d_in[1];   // [512,512,128]
    const int*   sidx = (const int*)  d_in[2];   // [512]

    cudaFuncSetAttribute(gemm_lse_hmma, cudaFuncAttributeMaxDynamicSharedMemorySize, SMEM_SZ);

    qconv<<<16, 256>>>(Q);
    gemm_lse_hmma<<<NTILES, 256, SMEM_SZ>>>(Km, sidx);
    reduce_all<<<BQ, 256>>>((float*)d_out);
}

// round 11
// speedup vs baseline: 1.1045x; 1.0561x over previous
#include <cuda_runtime.h>
#include <cuda_fp16.h>
#include <math.h>
#include <stdint.h>

// InfoNCE loss: single-pass fp16 HMMA GEMM (f32 acc) + fused online LSE.
// Warp tile 16m x 128n: full row per warp -> in-warp LSE, no cross-warp
// combine, 2 barriers/mb. Queries pre-scaled by 1/T; fused final reduce.
// Inputs: out f32 [512,128], keys f32 [512,512,128], self_index i32 [512]
// Output: scalar f32 loss.

#define BQ      512
#define DD      128
#define KPB     512
#define TILEN   128
#define NTILES  ((BQ * KPB) / TILEN)  // 2048
#define INV_T   14.285714285714285f
#define NEG_BIG -1.0e30f

// ---------------- global scratch (allocation-free rule) ----------------
__device__ __align__(256) __half g_qh[BQ * DD];          // queries * INV_T, fp16
__device__ float g_pm[BQ * NTILES], g_ps[BQ * NTILES];
__device__ float g_loss[BQ];
__device__ unsigned int g_done;                          // completion counter (self-resets)

// ---------------- PTX helpers ----------------
__device__ __forceinline__ uint32_t smem_u32(const void* p) {
    uint32_t a;
    asm("{ .reg .u64 t; cvta.to.shared.u64 t, %1; cvt.u32.u64 %0, t; }" : "=r"(a) : "l"(p));
    return a;
}
__device__ __forceinline__ void ldmx4(uint32_t* r, uint32_t addr) {
    asm volatile("ldmatrix.sync.aligned.m8n8.x4.shared.b16 {%0,%1,%2,%3}, [%4];"
                 : "=r"(r[0]), "=r"(r[1]), "=r"(r[2]), "=r"(r[3]) : "r"(addr));
}
__device__ __forceinline__ void hmma16816(float* c, const uint32_t* a, const uint32_t* b) {
    asm volatile("mma.sync.aligned.m16n8k16.row.col.f32.f16.f16.f32 "
                 "{%0,%1,%2,%3},{%4,%5,%6,%7},{%8,%9},{%0,%1,%2,%3};"
                 : "+f"(c[0]), "+f"(c[1]), "+f"(c[2]), "+f"(c[3])
                 : "r"(a[0]), "r"(a[1]), "r"(a[2]), "r"(a[3]), "r"(b[0]), "r"(b[1]));
}
#define CPASYNC16(s, g) asm volatile("cp.async.cg.shared.global [%0], [%1], 16;" :: "r"(s), "l"(g))
#define CP_COMMIT()     asm volatile("cp.async.commit_group;" ::: "memory")
#define CP_WAIT0()      asm volatile("cp.async.wait_group 0;" ::: "memory")

// ---------------------------------------------------------------------------
// Kernel 0: queries f32 -> fp16 * INV_T (folds temperature into A once).
// ---------------------------------------------------------------------------
__global__ __launch_bounds__(256)
void qconv(const float* __restrict__ Q)
{
    const int t = blockIdx.x * 256 + threadIdx.x;      // 4096 threads
    #pragma unroll
    for (int i = 0; i < 4; i++) {
        int f = t + i * 4096;                          // float4 index 0..16383
        float4 v = ((const float4*)Q)[f];
        __half2 h0 = __floats2half2_rn(v.x * INV_T, v.y * INV_T);
        __half2 h1 = __floats2half2_rn(v.z * INV_T, v.w * INV_T);
        ((uint2*)g_qh)[f] = make_uint2(*(uint32_t*)&h0, *(uint32_t*)&h1);
    }
}

// ---------------- SMEM layout ----------------
// tiles 128 rows x 128 fp16, padded stride 272 B (17 x 16B -> ldmatrix conflict-free)
#define TSTRIDE 272u
#define OFF_B   0u
#define OFF_A   34816u
#define SMEM_SZ 69632u

// cp.async one 128x128 fp16 tile from global fp16 (2048 16B chunks, 8/thread)
__device__ __forceinline__ void load_a_tile(uint32_t s_a, const __half* g, int rowBase, int tid)
{
    #pragma unroll
    for (int i = 0; i < 8; i++) {
        int idx = tid + i * 256;            // 0..2047
        int r   = idx >> 4;
        int c   = idx & 15;
        const char* gp = (const char*)g + (size_t)(rowBase + r) * 256 + c * 16;
        CPASYNC16(s_a + r * TSTRIDE + c * 16, gp);
    }
}

// ---------------------------------------------------------------------------
// Kernel 1: one CTA per 128-key tile; B converted f32->f16 in-CTA; 4 m-blocks
// of 128 queries, A prefetched during the epilogue. 8 warps, warp tile
// 16m x 128n: per-row LSE entirely in-warp (no cross-warp combine).
// ---------------------------------------------------------------------------
__global__ __launch_bounds__(256, 2)
void gemm_lse_hmma(const float* __restrict__ Km, const int* __restrict__ sidx)
{
    extern __shared__ char smem[];
    const uint32_t sb = smem_u32(smem);
    const int tid  = threadIdx.x;
    const int wid  = tid >> 5;
    const int lane = tid & 31;
    const int tile = blockIdx.x;
    const int colBase = tile * TILEN;

    // kick A(0) prefetch, then convert B tile f32 -> f16 smem (hides LDG latency)
    load_a_tile(sb + OFF_A, g_qh, 0, tid);
    CP_COMMIT();
    #pragma unroll
    for (int i = 0; i < 16; i++) {
        int f  = tid + i * 256;             // float4 index 0..4095 (32 per row)
        int r  = f >> 5;
        int c4 = f & 31;
        float4 v = *(const float4*)(Km + (size_t)(colBase + r) * DD + c4 * 4);
        __half2 h0 = __floats2half2_rn(v.x, v.y);
        __half2 h1 = __floats2half2_rn(v.z, v.w);
        *(uint2*)(smem + OFF_B + r * TSTRIDE + c4 * 8)
            = make_uint2(*(uint32_t*)&h0, *(uint32_t*)&h1);
    }
    CP_WAIT0();
    __syncthreads();

    #pragma unroll 1
    for (int mb = 0; mb < 4; mb++) {
        float acc[16][4];                   // ni 0..15 (n8 tiles), 4 regs each
        #pragma unroll
        for (int ni = 0; ni < 16; ni++)
            #pragma unroll
            for (int r = 0; r < 4; r++) acc[ni][r] = 0.0f;

        // A: this warp's 16 rows; B: all 128 key rows (8 x4-loads per kk)
        const uint32_t arow = sb + OFF_A + (wid * 16 + (lane & 15)) * TSTRIDE
                            + (lane >> 4) * 16;
        const uint32_t brow = sb + OFF_B + (lane & 15) * TSTRIDE + (lane >> 4) * 16;
        #pragma unroll
        for (int kk = 0; kk < 8; kk++) {                // 8 k-steps of 16 halves
            uint32_t a[4];
            ldmx4(a, arow + kk * 32);
            #pragma unroll
            for (int t = 0; t < 8; t++) {               // 16 key rows per t
                uint32_t bq[4];
                ldmx4(bq, brow + kk * 32 + t * 16 * TSTRIDE);
                uint32_t b0[2] = {bq[0], bq[2]};        // n8 tile 2t
                uint32_t b1[2] = {bq[1], bq[3]};        // n8 tile 2t+1
                hmma16816(acc[2 * t],     a, b0);
                hmma16816(acc[2 * t + 1], a, b1);
            }
        }

        __syncthreads();                    // all warps done reading A smem
        if (mb < 3) {                       // prefetch next A under the epilogue
            load_a_tile(sb + OFF_A, g_qh, (mb + 1) * 128, tid);
            CP_COMMIT();
        }

        // ---- epilogue: fully in-warp. rows r0 = wid*16 + (lane>>2), r1 = r0+8;
        //      thread's columns: ni*8 + 2*(lane&3) + {0,1} for ni 0..15.
        {
            const int r0l = wid * 16 + (lane >> 2);
            const int r1l = r0l + 8;
            const int q0 = mb * 128 + r0l, q1 = mb * 128 + r1l;
            const int msk0 = q0 * KPB + __ldg(&sidx[q0]) - colBase;
            const int msk1 = q1 * KPB + __ldg(&sidx[q1]) - colBase;
            float v0[32], v1[32];
            #pragma unroll
            for (int ni = 0; ni < 16; ni++) {
                const int c = ni * 8 + 2 * (lane & 3);
                float x0 = acc[ni][0]; if (c     == msk0) x0 = NEG_BIG;
                float x1 = acc[ni][1]; if (c + 1 == msk0) x1 = NEG_BIG;
                float y0 = acc[ni][2]; if (c     == msk1) y0 = NEG_BIG;
                float y1 = acc[ni][3]; if (c + 1 == msk1) y1 = NEG_BIG;
                v0[2 * ni] = x0; v0[2 * ni + 1] = x1;
                v1[2 * ni] = y0; v1[2 * ni + 1] = y1;
            }
            float m0 = -3.0e38f, m1 = -3.0e38f;
            #pragma unroll
            for (int j = 0; j < 32; j++) { m0 = fmaxf(m0, v0[j]); m1 = fmaxf(m1, v1[j]); }
            #pragma unroll
            for (int o = 1; o < 4; o <<= 1) {           // row max over the quad
                m0 = fmaxf(m0, __shfl_xor_sync(0xFFFFFFFFu, m0, o));
                m1 = fmaxf(m1, __shfl_xor_sync(0xFFFFFFFFu, m1, o));
            }
            float s0 = 0.0f, s1 = 0.0f;
            #pragma unroll
            for (int j = 0; j < 32; j++) {
                s0 += __expf(v0[j] - m0);
                s1 += __expf(v1[j] - m1);
            }
            #pragma unroll
            for (int o = 1; o < 4; o <<= 1) {           // row sum over the quad
                s0 += __shfl_xor_sync(0xFFFFFFFFu, s0, o);
                s1 += __shfl_xor_sync(0xFFFFFFFFu, s1, o);
            }
            if ((lane & 3) == 0) {
                g_pm[q0 * NTILES + tile] = m0; g_ps[q0 * NTILES + tile] = s0;
                g_pm[q1 * NTILES + tile] = m1; g_ps[q1 * NTILES + tile] = s1;
            }
        }
        CP_WAIT0();
        __syncthreads();                    // next A tile resident
    }
}

// ---------------------------------------------------------------------------
// Kernel 2 (fused): per query, reduce 2048 (m,s) partials -> total LSE;
// own-bag tiles (4b..4b+3) + 261632 exp(0) -> positive LSE; per-query loss.
// Last block sums g_loss in fixed order -> mean; counter self-resets.
// ---------------------------------------------------------------------------
__global__ void reduce_all(float* __restrict__ out)
{
    __shared__ float sm[256], ss[256];
    __shared__ unsigned int is_last;
    const int b = blockIdx.x, tid = threadIdx.x;

    float m = -3.0e38f, s = 0.0f;
    for (int t = tid; t < NTILES; t += 256) {
        float mo = g_pm[b * NTILES + t], so = g_ps[b * NTILES + t];
        float M = fmaxf(m, mo);
        s = s * __expf(m - M) + so * __expf(mo - M);
        m = M;
    }
    sm[tid] = m; ss[tid] = s;
    __syncthreads();
    for (int st = 128; st > 0; st >>= 1) {
        if (tid < st) {
            float m1 = sm[tid], m2 = sm[tid + st];
            float s1 = ss[tid], s2 = ss[tid + st];
            float M = fmaxf(m1, m2);
            sm[tid] = M;
            ss[tid] = s1 * __expf(m1 - M) + s2 * __expf(m2 - M);
        }
        __syncthreads();
    }
    if (tid == 0) {
        float lse_tot = sm[0] + logf(ss[0]);

        float mp = -3.0e38f, sp = 0.0f;
        #pragma unroll
        for (int p = 0; p < 4; p++) {                  // positive tiles = 4b..4b+3
            float mo = g_pm[b * NTILES + 4 * b + p];
            float so = g_ps[b * NTILES + 4 * b + p];
            float M = fmaxf(mp, mo);
            sp = sp * __expf(mp - M) + so * __expf(mo - M);
            mp = M;
        }
        // s_*labels keeps negatives as exp(0)=1: B*K - K = 261632 of them
        float Mp = fmaxf(mp, 0.0f);
        float Sp = sp * __expf(mp - Mp) + 261632.0f * __expf(-Mp);
        float lse_p = Mp + logf(Sp);

        g_loss[b] = -lse_p + logf(511.0f) + lse_tot;      // num_p = 512 -> 511

        __threadfence();
        is_last = (atomicAdd(&g_done, 1u) == BQ - 1) ? 1u : 0u;
    }
    __syncthreads();
    if (is_last) {                           // final mean, fixed order (deterministic)
        __threadfence();
        sm[tid] = g_loss[tid] + g_loss[tid + 256];
        __syncthreads();
        for (int st = 128; st > 0; st >>= 1) {
            if (tid < st) sm[tid] += sm[tid + st];
            __syncthreads();
        }
        if (tid == 0) {
            out[0] = sm[0] * (1.0f / 512.0f);
            g_done = 0;                      // reset for next graph replay
        }
    }
}

// ---------------------------------------------------------------------------
extern "C" void kernel_launch(void* const* d_in, const int* in_sizes, int n_in,
                              void* d_out, int out_size)
{
    const float* Q    = (const float*)d_in[0];   // [512,128]
    const float* Km   = (const float*)d_in[1];   // [512,512,128]
    const int*   sidx = (const int*)  d_in[2];   // [512]

    cudaFuncSetAttribute(gemm_lse_hmma, cudaFuncAttributeMaxDynamicSharedMemorySize, SMEM_SZ);

    qconv<<<16, 256>>>(Q);
    gemm_lse_hmma<<<NTILES, 256, SMEM_SZ>>>(Km, sidx);
    reduce_all<<<BQ, 256>>>((float*)d_out);
}